// round 1
// baseline (speedup 1.0000x reference)
#include <cuda_runtime.h>
#include <math.h>

// Problem constants
static constexpr int B_  = 2;
static constexpr int N_  = 2048;
static constexpr int C_  = 1024;
static constexpr int H_  = 16;
static constexpr int D_  = 64;
static constexpr int DFF = 4096;
static constexpr int M_  = B_ * N_;          // 4096 rows
static constexpr long long XSZ   = (long long)B_ * N_ * C_;          // 4,194,304
static constexpr long long ATTNSZ= (long long)B_ * H_ * N_ * N_;     // 134,217,728

// ---------------- scratch (device globals; no allocation allowed) ----------------
__device__ float g_xn [M_ * C_];        // ln1(x)
__device__ float g_qkv[M_ * 3 * C_];    // qkv projection
__device__ float g_ctx[M_ * C_];        // attention context (B,N,C layout)
__device__ float g_x1 [M_ * C_];        // x + attn_out (residual 1)
__device__ float g_hn [M_ * C_];        // ln2(x1)
__device__ float g_ff [M_ * DFF];       // gelu(fc1)
__device__ float g_attn_fallback[ATTNSZ]; // only used if out buffer lacks attn

// ---------------- block reduction helpers ----------------
__device__ __forceinline__ float blockReduceSum(float val, float* shbuf) {
    int lane = threadIdx.x & 31, wid = threadIdx.x >> 5;
#pragma unroll
    for (int o = 16; o > 0; o >>= 1) val += __shfl_xor_sync(0xffffffffu, val, o);
    if (lane == 0) shbuf[wid] = val;
    __syncthreads();
    if (wid == 0) {
        val = (lane < 8) ? shbuf[lane] : 0.0f;
#pragma unroll
        for (int o = 4; o > 0; o >>= 1) val += __shfl_xor_sync(0xffffffffu, val, o);
        if (lane == 0) shbuf[0] = val;
    }
    __syncthreads();
    float r = shbuf[0];
    __syncthreads();
    return r;
}

__device__ __forceinline__ float blockReduceMax(float val, float* shbuf) {
    int lane = threadIdx.x & 31, wid = threadIdx.x >> 5;
#pragma unroll
    for (int o = 16; o > 0; o >>= 1) val = fmaxf(val, __shfl_xor_sync(0xffffffffu, val, o));
    if (lane == 0) shbuf[wid] = val;
    __syncthreads();
    if (wid == 0) {
        val = (lane < 8) ? shbuf[lane] : -INFINITY;
#pragma unroll
        for (int o = 4; o > 0; o >>= 1) val = fmaxf(val, __shfl_xor_sync(0xffffffffu, val, o));
        if (lane == 0) shbuf[0] = val;
    }
    __syncthreads();
    float r = shbuf[0];
    __syncthreads();
    return r;
}

// ---------------- layernorm: one block per row, C=1024, 256 threads ----------------
__global__ __launch_bounds__(256)
void ln_kernel(const float* __restrict__ x, const float* __restrict__ g,
               const float* __restrict__ b, float* __restrict__ out) {
    __shared__ float sh[8];
    long long row = blockIdx.x;
    const float* xr = x + row * C_;
    float* orow = out + row * C_;
    int t = threadIdx.x;
    float v[4];
    float s = 0.0f;
#pragma unroll
    for (int i = 0; i < 4; i++) { v[i] = xr[t + i * 256]; s += v[i]; }
    s = blockReduceSum(s, sh);
    float mu = s * (1.0f / C_);
    float var = 0.0f;
#pragma unroll
    for (int i = 0; i < 4; i++) { float d = v[i] - mu; var += d * d; }
    var = blockReduceSum(var, sh);
    float r = rsqrtf(var * (1.0f / C_) + 1e-5f);
#pragma unroll
    for (int i = 0; i < 4; i++) {
        int c = t + i * 256;
        orow[c] = (v[i] - mu) * r * g[c] + b[c];
    }
}

// ---------------- row softmax over 2048 cols ----------------
__global__ __launch_bounds__(256)
void softmax_kernel(float* __restrict__ attn) {
    __shared__ float sh[8];
    long long row = blockIdx.x;
    float* p = attn + row * (long long)N_;
    int t = threadIdx.x;
    float v[8];
    float mx = -INFINITY;
#pragma unroll
    for (int i = 0; i < 8; i++) { v[i] = p[t + i * 256]; mx = fmaxf(mx, v[i]); }
    mx = blockReduceMax(mx, sh);
    float s = 0.0f;
#pragma unroll
    for (int i = 0; i < 8; i++) { v[i] = __expf(v[i] - mx); s += v[i]; }
    s = blockReduceSum(s, sh);
    float inv = 1.0f / s;
#pragma unroll
    for (int i = 0; i < 8; i++) p[t + i * 256] = v[i] * inv;
}

// ---------------- GEMM: C[M,Nc] = A[M,K] @ Bm[Nc,K]^T  (weights row-major [out,in]) ----
// Batched via blockIdx.z with split (outer=z/Hdiv, inner=z%Hdiv) strides, so
// non-rectangular batch offsets (b*strideB + h*strideH) are expressible.
enum { EPI_NONE = 0, EPI_BIAS_GELU = 1, EPI_BIAS_RES = 2, EPI_SCORE = 3 };

template <int EPI>
__global__ __launch_bounds__(256)
void gemm_abt(const float* __restrict__ A, const float* __restrict__ Bm,
              float* __restrict__ Cm,
              int K, int lda, int ldb, int ldc,
              long long aOut, long long aIn, long long bOut, long long bIn,
              long long cOut, long long cIn, int Hdiv,
              const float* __restrict__ bias, const float* __restrict__ resid,
              float scale, const int* __restrict__ mask, int maskld) {
    int z = blockIdx.z;
    int zb = z / Hdiv, zh = z % Hdiv;
    A  += (long long)zb * aOut + (long long)zh * aIn;
    Bm += (long long)zb * bOut + (long long)zh * bIn;
    Cm += (long long)zb * cOut + (long long)zh * cIn;

    __shared__ float As[16][68];
    __shared__ float Ws[16][68];
    int t  = threadIdx.x;
    int tx = t & 15, ty = t >> 4;
    int m0 = blockIdx.y * 64, n0 = blockIdx.x * 64;
    int arow = t >> 2, acol = (t & 3) * 4;

    float acc[4][4] = {};
    for (int k0 = 0; k0 < K; k0 += 16) {
        float4 av = *(const float4*)&A [(long long)(m0 + arow) * lda + k0 + acol];
        float4 bv = *(const float4*)&Bm[(long long)(n0 + arow) * ldb + k0 + acol];
        __syncthreads();
        As[acol + 0][arow] = av.x; As[acol + 1][arow] = av.y;
        As[acol + 2][arow] = av.z; As[acol + 3][arow] = av.w;
        Ws[acol + 0][arow] = bv.x; Ws[acol + 1][arow] = bv.y;
        Ws[acol + 2][arow] = bv.z; Ws[acol + 3][arow] = bv.w;
        __syncthreads();
#pragma unroll
        for (int kk = 0; kk < 16; kk++) {
            float a0 = As[kk][ty * 4 + 0], a1 = As[kk][ty * 4 + 1];
            float a2 = As[kk][ty * 4 + 2], a3 = As[kk][ty * 4 + 3];
            float b0 = Ws[kk][tx * 4 + 0], b1 = Ws[kk][tx * 4 + 1];
            float b2 = Ws[kk][tx * 4 + 2], b3 = Ws[kk][tx * 4 + 3];
            acc[0][0] += a0 * b0; acc[0][1] += a0 * b1; acc[0][2] += a0 * b2; acc[0][3] += a0 * b3;
            acc[1][0] += a1 * b0; acc[1][1] += a1 * b1; acc[1][2] += a1 * b2; acc[1][3] += a1 * b3;
            acc[2][0] += a2 * b0; acc[2][1] += a2 * b1; acc[2][2] += a2 * b2; acc[2][3] += a2 * b3;
            acc[3][0] += a3 * b0; acc[3][1] += a3 * b1; acc[3][2] += a3 * b2; acc[3][3] += a3 * b3;
        }
    }

    const int* mrow = (EPI == EPI_SCORE) ? mask + (long long)zb * maskld : nullptr;
#pragma unroll
    for (int i = 0; i < 4; i++) {
        int mg = m0 + ty * 4 + i;
#pragma unroll
        for (int j = 0; j < 4; j++) {
            int ng = n0 + tx * 4 + j;
            float v = acc[i][j];
            if (EPI == EPI_SCORE) {
                v *= scale;
                if (mrow[ng] == 0) v = -INFINITY;
            } else if (EPI == EPI_BIAS_GELU) {
                v += bias[ng];
                v = 0.5f * v * (1.0f + erff(v * 0.70710678118654752f));
            } else if (EPI == EPI_BIAS_RES) {
                v += bias[ng] + resid[(long long)mg * ldc + ng];
            }
            Cm[(long long)mg * ldc + ng] = v;
        }
    }
}

// ---------------- GEMM: C[M,Nc] = A[M,K] @ Bm[K,Nc]  (attn @ V) ----------------
__global__ __launch_bounds__(256)
void gemm_ab(const float* __restrict__ A, const float* __restrict__ Bm,
             float* __restrict__ Cm,
             int K, int lda, int ldb, int ldc,
             long long aOut, long long aIn, long long bOut, long long bIn,
             long long cOut, long long cIn, int Hdiv) {
    int z = blockIdx.z;
    int zb = z / Hdiv, zh = z % Hdiv;
    A  += (long long)zb * aOut + (long long)zh * aIn;
    Bm += (long long)zb * bOut + (long long)zh * bIn;
    Cm += (long long)zb * cOut + (long long)zh * cIn;

    __shared__ float As[16][68];
    __shared__ float Ws[16][68];
    int t  = threadIdx.x;
    int tx = t & 15, ty = t >> 4;
    int m0 = blockIdx.y * 64, n0 = blockIdx.x * 64;
    int arow = t >> 2, acol = (t & 3) * 4;   // A tile: 64 rows x 16 k
    int brow = t >> 4, bcol = (t & 15) * 4;  // B tile: 16 k x 64 cols

    float acc[4][4] = {};
    for (int k0 = 0; k0 < K; k0 += 16) {
        float4 av = *(const float4*)&A [(long long)(m0 + arow) * lda + k0 + acol];
        float4 bv = *(const float4*)&Bm[(long long)(k0 + brow) * ldb + n0 + bcol];
        __syncthreads();
        As[acol + 0][arow] = av.x; As[acol + 1][arow] = av.y;
        As[acol + 2][arow] = av.z; As[acol + 3][arow] = av.w;
        Ws[brow][bcol + 0] = bv.x; Ws[brow][bcol + 1] = bv.y;
        Ws[brow][bcol + 2] = bv.z; Ws[brow][bcol + 3] = bv.w;
        __syncthreads();
#pragma unroll
        for (int kk = 0; kk < 16; kk++) {
            float a0 = As[kk][ty * 4 + 0], a1 = As[kk][ty * 4 + 1];
            float a2 = As[kk][ty * 4 + 2], a3 = As[kk][ty * 4 + 3];
            float b0 = Ws[kk][tx * 4 + 0], b1 = Ws[kk][tx * 4 + 1];
            float b2 = Ws[kk][tx * 4 + 2], b3 = Ws[kk][tx * 4 + 3];
            acc[0][0] += a0 * b0; acc[0][1] += a0 * b1; acc[0][2] += a0 * b2; acc[0][3] += a0 * b3;
            acc[1][0] += a1 * b0; acc[1][1] += a1 * b1; acc[1][2] += a1 * b2; acc[1][3] += a1 * b3;
            acc[2][0] += a2 * b0; acc[2][1] += a2 * b1; acc[2][2] += a2 * b2; acc[2][3] += a2 * b3;
            acc[3][0] += a3 * b0; acc[3][1] += a3 * b1; acc[3][2] += a3 * b2; acc[3][3] += a3 * b3;
        }
    }
#pragma unroll
    for (int i = 0; i < 4; i++) {
        int mg = m0 + ty * 4 + i;
#pragma unroll
        for (int j = 0; j < 4; j++) {
            int ng = n0 + tx * 4 + j;
            Cm[(long long)mg * ldc + ng] = acc[i][j];
        }
    }
}

// ---------------- launch ----------------
extern "C" void kernel_launch(void* const* d_in, const int* in_sizes, int n_in,
                              void* d_out, int out_size) {
    const float* x      = (const float*)d_in[0];
    const int*   mask   = (const int*)  d_in[1];
    const float* qkv_w  = (const float*)d_in[2];
    const float* proj_w = (const float*)d_in[3];
    const float* proj_b = (const float*)d_in[4];
    const float* ln1_g  = (const float*)d_in[5];
    const float* ln1_b  = (const float*)d_in[6];
    const float* ln2_g  = (const float*)d_in[7];
    const float* ln2_b  = (const float*)d_in[8];
    const float* fc1_w  = (const float*)d_in[9];
    const float* fc1_b  = (const float*)d_in[10];
    const float* fc2_w  = (const float*)d_in[11];
    const float* fc2_b  = (const float*)d_in[12];

    float* out_x = (float*)d_out;

    float* xn;  cudaGetSymbolAddress((void**)&xn,  g_xn);
    float* qkv; cudaGetSymbolAddress((void**)&qkv, g_qkv);
    float* ctx; cudaGetSymbolAddress((void**)&ctx, g_ctx);
    float* x1;  cudaGetSymbolAddress((void**)&x1,  g_x1);
    float* hn;  cudaGetSymbolAddress((void**)&hn,  g_hn);
    float* ff;  cudaGetSymbolAddress((void**)&ff,  g_ff);
    float* attn_fb; cudaGetSymbolAddress((void**)&attn_fb, g_attn_fallback);

    float* attn = ((long long)out_size >= XSZ + ATTNSZ) ? (out_x + XSZ) : attn_fb;

    const float scale = 0.125f;  // D^-0.5 = 1/8

    // 1) ln1(x) -> xn
    ln_kernel<<<M_, 256>>>(x, ln1_g, ln1_b, xn);

    // 2) qkv = xn @ qkv_w^T   [4096 x 3072], K=1024
    gemm_abt<EPI_NONE><<<dim3(3 * C_ / 64, M_ / 64, 1), 256>>>(
        xn, qkv_w, qkv, C_, C_, C_, 3 * C_,
        0, 0, 0, 0, 0, 0, 1, nullptr, nullptr, 0.f, nullptr, 0);

    // 3) scores[b,h,n,m] = scale * q·k, masked -> attn region of d_out
    //    q base = qkv + b*N*3C + h*D ; k base = qkv + b*N*3C + C + h*D
    gemm_abt<EPI_SCORE><<<dim3(N_ / 64, N_ / 64, B_ * H_), 256>>>(
        qkv, qkv + C_, attn, D_, 3 * C_, 3 * C_, N_,
        (long long)N_ * 3 * C_, D_,            // A: b-stride, h-stride
        (long long)N_ * 3 * C_, D_,            // B: b-stride, h-stride
        (long long)H_ * N_ * N_, (long long)N_ * N_,  // C: b-stride, h-stride
        H_, nullptr, nullptr, scale, mask, N_);

    // 4) softmax over last dim
    softmax_kernel<<<B_ * H_ * N_, 256>>>(attn);

    // 5) ctx[b,n,h*D+d] = attn @ v   (per b,h: [2048,2048] @ [2048,64])
    gemm_ab<<<dim3(1, N_ / 64, B_ * H_), 256>>>(
        attn, qkv + 2 * C_, ctx, N_, N_, 3 * C_, C_,
        (long long)H_ * N_ * N_, (long long)N_ * N_,  // A strides
        (long long)N_ * 3 * C_, D_,                   // B (v) strides
        (long long)N_ * C_, D_,                       // C strides
        H_);

    // 6) x1 = x + ctx @ proj_w^T + proj_b
    gemm_abt<EPI_BIAS_RES><<<dim3(C_ / 64, M_ / 64, 1), 256>>>(
        ctx, proj_w, x1, C_, C_, C_, C_,
        0, 0, 0, 0, 0, 0, 1, proj_b, x, 0.f, nullptr, 0);

    // 7) ln2(x1) -> hn
    ln_kernel<<<M_, 256>>>(x1, ln2_g, ln2_b, hn);

    // 8) ff = gelu(hn @ fc1_w^T + fc1_b)   [4096 x 4096], K=1024
    gemm_abt<EPI_BIAS_GELU><<<dim3(DFF / 64, M_ / 64, 1), 256>>>(
        hn, fc1_w, ff, C_, C_, C_, DFF,
        0, 0, 0, 0, 0, 0, 1, fc1_b, nullptr, 0.f, nullptr, 0);

    // 9) out_x = x1 + ff @ fc2_w^T + fc2_b   [4096 x 1024], K=4096
    gemm_abt<EPI_BIAS_RES><<<dim3(C_ / 64, M_ / 64, 1), 256>>>(
        ff, fc2_w, out_x, DFF, DFF, DFF, C_,
        0, 0, 0, 0, 0, 0, 1, fc2_b, x1, 0.f, nullptr, 0);
}

// round 2
// speedup vs baseline: 1.1238x; 1.1238x over previous
#include <cuda_runtime.h>
#include <math.h>

// Problem constants
static constexpr int B_  = 2;
static constexpr int N_  = 2048;
static constexpr int C_  = 1024;
static constexpr int H_  = 16;
static constexpr int D_  = 64;
static constexpr int DFF = 4096;
static constexpr int M_  = B_ * N_;          // 4096 rows
static constexpr long long XSZ   = (long long)B_ * N_ * C_;          // 4,194,304
static constexpr long long ATTNSZ= (long long)B_ * H_ * N_ * N_;     // 134,217,728

// ---------------- scratch (device globals; no allocation allowed) ----------------
__device__ float g_xn [M_ * C_];        // ln1(x)
__device__ float g_qkv[M_ * 3 * C_];    // qkv projection
__device__ float g_ctx[M_ * C_];        // attention context (B,N,C layout)
__device__ float g_x1 [M_ * C_];        // x + attn_out (residual 1)
__device__ float g_hn [M_ * C_];        // ln2(x1)
__device__ float g_ff [M_ * DFF];       // gelu(fc1)
__device__ float g_attn_fallback[ATTNSZ]; // only used if out buffer lacks attn

// ---------------- block reduction helpers ----------------
__device__ __forceinline__ float blockReduceSum(float val, float* shbuf) {
    int lane = threadIdx.x & 31, wid = threadIdx.x >> 5;
#pragma unroll
    for (int o = 16; o > 0; o >>= 1) val += __shfl_xor_sync(0xffffffffu, val, o);
    if (lane == 0) shbuf[wid] = val;
    __syncthreads();
    if (wid == 0) {
        val = (lane < 8) ? shbuf[lane] : 0.0f;
#pragma unroll
        for (int o = 4; o > 0; o >>= 1) val += __shfl_xor_sync(0xffffffffu, val, o);
        if (lane == 0) shbuf[0] = val;
    }
    __syncthreads();
    float r = shbuf[0];
    __syncthreads();
    return r;
}

__device__ __forceinline__ float blockReduceMax(float val, float* shbuf) {
    int lane = threadIdx.x & 31, wid = threadIdx.x >> 5;
#pragma unroll
    for (int o = 16; o > 0; o >>= 1) val = fmaxf(val, __shfl_xor_sync(0xffffffffu, val, o));
    if (lane == 0) shbuf[wid] = val;
    __syncthreads();
    if (wid == 0) {
        val = (lane < 8) ? shbuf[lane] : -INFINITY;
#pragma unroll
        for (int o = 4; o > 0; o >>= 1) val = fmaxf(val, __shfl_xor_sync(0xffffffffu, val, o));
        if (lane == 0) shbuf[0] = val;
    }
    __syncthreads();
    float r = shbuf[0];
    __syncthreads();
    return r;
}

// ---------------- layernorm: one block per row, C=1024, 256 threads ----------------
__global__ __launch_bounds__(256)
void ln_kernel(const float* __restrict__ x, const float* __restrict__ g,
               const float* __restrict__ b, float* __restrict__ out) {
    __shared__ float sh[8];
    long long row = blockIdx.x;
    const float* xr = x + row * C_;
    float* orow = out + row * C_;
    int t = threadIdx.x;
    float v[4];
    float s = 0.0f;
#pragma unroll
    for (int i = 0; i < 4; i++) { v[i] = xr[t + i * 256]; s += v[i]; }
    s = blockReduceSum(s, sh);
    float mu = s * (1.0f / C_);
    float var = 0.0f;
#pragma unroll
    for (int i = 0; i < 4; i++) { float d = v[i] - mu; var += d * d; }
    var = blockReduceSum(var, sh);
    float r = rsqrtf(var * (1.0f / C_) + 1e-5f);
#pragma unroll
    for (int i = 0; i < 4; i++) {
        int c = t + i * 256;
        orow[c] = (v[i] - mu) * r * g[c] + b[c];
    }
}

// ---------------- row softmax over 2048 cols ----------------
__global__ __launch_bounds__(256)
void softmax_kernel(float* __restrict__ attn) {
    __shared__ float sh[8];
    long long row = blockIdx.x;
    float* p = attn + row * (long long)N_;
    int t = threadIdx.x;
    float v[8];
    float mx = -INFINITY;
#pragma unroll
    for (int i = 0; i < 8; i++) { v[i] = p[t + i * 256]; mx = fmaxf(mx, v[i]); }
    mx = blockReduceMax(mx, sh);
    float s = 0.0f;
#pragma unroll
    for (int i = 0; i < 8; i++) { v[i] = __expf(v[i] - mx); s += v[i]; }
    s = blockReduceSum(s, sh);
    float inv = 1.0f / s;
#pragma unroll
    for (int i = 0; i < 8; i++) p[t + i * 256] = v[i] * inv;
}

// ---------------- epilogue ids ----------------
enum { EPI_NONE = 0, EPI_BIAS_GELU = 1, EPI_BIAS_RES = 2, EPI_SCORE = 3 };

// ============================================================================
// GEMM: C[M,Nc] = A[M,K] @ Bm[Nc,K]^T    (torch Linear weight layout [out,in])
// 128x128 block tile, 8x8 per thread, K-step 8, double-buffered smem.
// Requires: M % 128 == 0, Nc % 128 == 0, K % 8 == 0.
// ============================================================================
template <int EPI>
__global__ __launch_bounds__(256, 2)
void gemm_abt128(const float* __restrict__ A, const float* __restrict__ Bm,
                 float* __restrict__ Cm,
                 int K, int lda, int ldb, int ldc,
                 long long aOut, long long aIn, long long bOut, long long bIn,
                 long long cOut, long long cIn, int Hdiv,
                 const float* __restrict__ bias, const float* __restrict__ resid,
                 float scale, const int* __restrict__ mask, int maskld) {
    int z = blockIdx.z;
    int zb = z / Hdiv, zh = z % Hdiv;
    A  += (long long)zb * aOut + (long long)zh * aIn;
    Bm += (long long)zb * bOut + (long long)zh * bIn;
    Cm += (long long)zb * cOut + (long long)zh * cIn;

    __shared__ float As[2][8][132];
    __shared__ float Ws[2][8][132];

    int t  = threadIdx.x;
    int tx = t & 15, ty = t >> 4;
    int m0 = blockIdx.y * 128, n0 = blockIdx.x * 128;

    int ldrow = t >> 1;          // 0..127
    int ldk   = (t & 1) * 4;     // 0 or 4
    const float* Aptr = A  + (long long)(m0 + ldrow) * lda + ldk;
    const float* Bptr = Bm + (long long)(n0 + ldrow) * ldb + ldk;

    // preload tile 0
    float4 ar = *(const float4*)Aptr;
    float4 br = *(const float4*)Bptr;
    As[0][ldk + 0][ldrow] = ar.x; As[0][ldk + 1][ldrow] = ar.y;
    As[0][ldk + 2][ldrow] = ar.z; As[0][ldk + 3][ldrow] = ar.w;
    Ws[0][ldk + 0][ldrow] = br.x; Ws[0][ldk + 1][ldrow] = br.y;
    Ws[0][ldk + 2][ldrow] = br.z; Ws[0][ldk + 3][ldrow] = br.w;
    __syncthreads();

    float acc[8][8] = {};
    int KT = K >> 3;
    int cur = 0;
    for (int kt = 0; kt < KT; kt++) {
        if (kt + 1 < KT) {
            ar = *(const float4*)(Aptr + (kt + 1) * 8);
            br = *(const float4*)(Bptr + (kt + 1) * 8);
        }
#pragma unroll
        for (int kk = 0; kk < 8; kk++) {
            float4 a0 = *(const float4*)&As[cur][kk][ty * 8];
            float4 a1 = *(const float4*)&As[cur][kk][ty * 8 + 4];
            float4 b0 = *(const float4*)&Ws[cur][kk][tx * 8];
            float4 b1 = *(const float4*)&Ws[cur][kk][tx * 8 + 4];
            float a[8] = {a0.x, a0.y, a0.z, a0.w, a1.x, a1.y, a1.z, a1.w};
            float b[8] = {b0.x, b0.y, b0.z, b0.w, b1.x, b1.y, b1.z, b1.w};
#pragma unroll
            for (int i = 0; i < 8; i++)
#pragma unroll
                for (int j = 0; j < 8; j++)
                    acc[i][j] += a[i] * b[j];
        }
        if (kt + 1 < KT) {
            int nxt = cur ^ 1;
            As[nxt][ldk + 0][ldrow] = ar.x; As[nxt][ldk + 1][ldrow] = ar.y;
            As[nxt][ldk + 2][ldrow] = ar.z; As[nxt][ldk + 3][ldrow] = ar.w;
            Ws[nxt][ldk + 0][ldrow] = br.x; Ws[nxt][ldk + 1][ldrow] = br.y;
            Ws[nxt][ldk + 2][ldrow] = br.z; Ws[nxt][ldk + 3][ldrow] = br.w;
            __syncthreads();
            cur = nxt;
        }
    }

    // epilogue
    const int* mrow = (EPI == EPI_SCORE) ? mask + (long long)zb * maskld : nullptr;
    float mj[8];
    if (EPI == EPI_SCORE) {
#pragma unroll
        for (int j = 0; j < 8; j++) mj[j] = (mrow[n0 + tx * 8 + j] == 0) ? 1.0f : 0.0f;
    }
    float bj[8];
    if (EPI == EPI_BIAS_GELU || EPI == EPI_BIAS_RES) {
#pragma unroll
        for (int j = 0; j < 8; j++) bj[j] = bias[n0 + tx * 8 + j];
    }
#pragma unroll
    for (int i = 0; i < 8; i++) {
        int mg = m0 + ty * 8 + i;
        long long base = (long long)mg * ldc + n0 + tx * 8;
        float v[8];
#pragma unroll
        for (int j = 0; j < 8; j++) {
            float x = acc[i][j];
            if (EPI == EPI_SCORE) {
                x *= scale;
                if (mj[j] != 0.0f) x = -INFINITY;
            } else if (EPI == EPI_BIAS_GELU) {
                x += bj[j];
                x = 0.5f * x * (1.0f + erff(x * 0.70710678118654752f));
            } else if (EPI == EPI_BIAS_RES) {
                x += bj[j] + resid[base + j];
            }
            v[j] = x;
        }
        *(float4*)&Cm[base]     = make_float4(v[0], v[1], v[2], v[3]);
        *(float4*)&Cm[base + 4] = make_float4(v[4], v[5], v[6], v[7]);
    }
}

// ============================================================================
// GEMM: C[M,64] = A[M,K] @ Bm[K,64]    (attn @ V; Nc fixed at 64 = D)
// 128x64 block tile, 8x4 per thread, K-step 8, double-buffered smem.
// ============================================================================
__global__ __launch_bounds__(256, 2)
void gemm_ab_n64(const float* __restrict__ A, const float* __restrict__ Bm,
                 float* __restrict__ Cm,
                 int K, int lda, int ldb, int ldc,
                 long long aOut, long long aIn, long long bOut, long long bIn,
                 long long cOut, long long cIn, int Hdiv) {
    int z = blockIdx.z;
    int zb = z / Hdiv, zh = z % Hdiv;
    A  += (long long)zb * aOut + (long long)zh * aIn;
    Bm += (long long)zb * bOut + (long long)zh * bIn;
    Cm += (long long)zb * cOut + (long long)zh * cIn;

    __shared__ float As[2][8][132];
    __shared__ float Ws[2][8][68];

    int t  = threadIdx.x;
    int tx = t & 15, ty = t >> 4;
    int m0 = blockIdx.y * 128;

    int ldrow = t >> 1;          // 0..127 (A tile row)
    int ldk   = (t & 1) * 4;     // 0 or 4 (A tile k)
    int bkr   = t >> 5;          // 0..7   (B tile k row)
    int bcol  = (t & 31) * 2;    // 0..62  (B tile col)
    const float*  Aptr = A  + (long long)(m0 + ldrow) * lda + ldk;
    const float*  Bptr = Bm + (long long)bkr * ldb + bcol;

    float4 ar = *(const float4*)Aptr;
    float2 br = *(const float2*)Bptr;
    As[0][ldk + 0][ldrow] = ar.x; As[0][ldk + 1][ldrow] = ar.y;
    As[0][ldk + 2][ldrow] = ar.z; As[0][ldk + 3][ldrow] = ar.w;
    Ws[0][bkr][bcol] = br.x; Ws[0][bkr][bcol + 1] = br.y;
    __syncthreads();

    float acc[8][4] = {};
    int KT = K >> 3;
    int cur = 0;
    for (int kt = 0; kt < KT; kt++) {
        if (kt + 1 < KT) {
            ar = *(const float4*)(Aptr + (kt + 1) * 8);
            br = *(const float2*)(Bptr + (long long)(kt + 1) * 8 * ldb);
        }
#pragma unroll
        for (int kk = 0; kk < 8; kk++) {
            float4 a0 = *(const float4*)&As[cur][kk][ty * 8];
            float4 a1 = *(const float4*)&As[cur][kk][ty * 8 + 4];
            float4 b0 = *(const float4*)&Ws[cur][kk][tx * 4];
            float a[8] = {a0.x, a0.y, a0.z, a0.w, a1.x, a1.y, a1.z, a1.w};
            float b[4] = {b0.x, b0.y, b0.z, b0.w};
#pragma unroll
            for (int i = 0; i < 8; i++)
#pragma unroll
                for (int j = 0; j < 4; j++)
                    acc[i][j] += a[i] * b[j];
        }
        if (kt + 1 < KT) {
            int nxt = cur ^ 1;
            As[nxt][ldk + 0][ldrow] = ar.x; As[nxt][ldk + 1][ldrow] = ar.y;
            As[nxt][ldk + 2][ldrow] = ar.z; As[nxt][ldk + 3][ldrow] = ar.w;
            Ws[nxt][bkr][bcol] = br.x; Ws[nxt][bkr][bcol + 1] = br.y;
            __syncthreads();
            cur = nxt;
        }
    }

#pragma unroll
    for (int i = 0; i < 8; i++) {
        int mg = m0 + ty * 8 + i;
        long long base = (long long)mg * ldc + tx * 4;
        *(float4*)&Cm[base] = make_float4(acc[i][0], acc[i][1], acc[i][2], acc[i][3]);
    }
}

// ---------------- launch ----------------
extern "C" void kernel_launch(void* const* d_in, const int* in_sizes, int n_in,
                              void* d_out, int out_size) {
    const float* x      = (const float*)d_in[0];
    const int*   mask   = (const int*)  d_in[1];
    const float* qkv_w  = (const float*)d_in[2];
    const float* proj_w = (const float*)d_in[3];
    const float* proj_b = (const float*)d_in[4];
    const float* ln1_g  = (const float*)d_in[5];
    const float* ln1_b  = (const float*)d_in[6];
    const float* ln2_g  = (const float*)d_in[7];
    const float* ln2_b  = (const float*)d_in[8];
    const float* fc1_w  = (const float*)d_in[9];
    const float* fc1_b  = (const float*)d_in[10];
    const float* fc2_w  = (const float*)d_in[11];
    const float* fc2_b  = (const float*)d_in[12];

    float* out_x = (float*)d_out;

    float* xn;  cudaGetSymbolAddress((void**)&xn,  g_xn);
    float* qkv; cudaGetSymbolAddress((void**)&qkv, g_qkv);
    float* ctx; cudaGetSymbolAddress((void**)&ctx, g_ctx);
    float* x1;  cudaGetSymbolAddress((void**)&x1,  g_x1);
    float* hn;  cudaGetSymbolAddress((void**)&hn,  g_hn);
    float* ff;  cudaGetSymbolAddress((void**)&ff,  g_ff);
    float* attn_fb; cudaGetSymbolAddress((void**)&attn_fb, g_attn_fallback);

    float* attn = ((long long)out_size >= XSZ + ATTNSZ) ? (out_x + XSZ) : attn_fb;

    const float scale = 0.125f;  // D^-0.5 = 1/8

    // 1) ln1(x) -> xn
    ln_kernel<<<M_, 256>>>(x, ln1_g, ln1_b, xn);

    // 2) qkv = xn @ qkv_w^T   [4096 x 3072], K=1024
    gemm_abt128<EPI_NONE><<<dim3(3 * C_ / 128, M_ / 128, 1), 256>>>(
        xn, qkv_w, qkv, C_, C_, C_, 3 * C_,
        0, 0, 0, 0, 0, 0, 1, nullptr, nullptr, 0.f, nullptr, 0);

    // 3) scores[b,h,n,m] = scale * q·k, masked -> attn region
    gemm_abt128<EPI_SCORE><<<dim3(N_ / 128, N_ / 128, B_ * H_), 256>>>(
        qkv, qkv + C_, attn, D_, 3 * C_, 3 * C_, N_,
        (long long)N_ * 3 * C_, D_,
        (long long)N_ * 3 * C_, D_,
        (long long)H_ * N_ * N_, (long long)N_ * N_,
        H_, nullptr, nullptr, scale, mask, N_);

    // 4) softmax over last dim
    softmax_kernel<<<B_ * H_ * N_, 256>>>(attn);

    // 5) ctx[b,n,h*D+d] = attn @ v   (per b,h: [2048,2048] @ [2048,64])
    gemm_ab_n64<<<dim3(1, N_ / 128, B_ * H_), 256>>>(
        attn, qkv + 2 * C_, ctx, N_, N_, 3 * C_, C_,
        (long long)H_ * N_ * N_, (long long)N_ * N_,
        (long long)N_ * 3 * C_, D_,
        (long long)N_ * C_, D_,
        H_);

    // 6) x1 = x + ctx @ proj_w^T + proj_b
    gemm_abt128<EPI_BIAS_RES><<<dim3(C_ / 128, M_ / 128, 1), 256>>>(
        ctx, proj_w, x1, C_, C_, C_, C_,
        0, 0, 0, 0, 0, 0, 1, proj_b, x, 0.f, nullptr, 0);

    // 7) ln2(x1) -> hn
    ln_kernel<<<M_, 256>>>(x1, ln2_g, ln2_b, hn);

    // 8) ff = gelu(hn @ fc1_w^T + fc1_b)   [4096 x 4096], K=1024
    gemm_abt128<EPI_BIAS_GELU><<<dim3(DFF / 128, M_ / 128, 1), 256>>>(
        hn, fc1_w, ff, C_, C_, C_, DFF,
        0, 0, 0, 0, 0, 0, 1, fc1_b, nullptr, 0.f, nullptr, 0);

    // 9) out_x = x1 + ff @ fc2_w^T + fc2_b   [4096 x 1024], K=4096
    gemm_abt128<EPI_BIAS_RES><<<dim3(C_ / 128, M_ / 128, 1), 256>>>(
        ff, fc2_w, out_x, DFF, DFF, DFF, C_,
        0, 0, 0, 0, 0, 0, 1, fc2_b, x1, 0.f, nullptr, 0);
}

// round 4
// speedup vs baseline: 1.6521x; 1.4700x over previous
#include <cuda_runtime.h>
#include <cuda_bf16.h>
#include <mma.h>
#include <cstdint>
#include <math.h>

using namespace nvcuda;

// Problem constants
static constexpr int B_  = 2;
static constexpr int N_  = 2048;
static constexpr int C_  = 1024;
static constexpr int H_  = 16;
static constexpr int D_  = 64;
static constexpr int DFF = 4096;
static constexpr int M_  = B_ * N_;
static constexpr long long XSZ   = (long long)B_ * N_ * C_;
static constexpr long long ATTNSZ= (long long)B_ * H_ * N_ * N_;

// ---------------- scratch (device globals) ----------------
__device__ __align__(256) float g_x1 [M_ * C_];
__device__ __align__(256) float g_attn_fallback[ATTNSZ];
__device__ __align__(256) __nv_bfloat16 g_xnh [M_ * C_],     g_xnl [M_ * C_];
__device__ __align__(256) __nv_bfloat16 g_qkvh[M_ * 3 * C_], g_qkvl[M_ * 3 * C_];
__device__ __align__(256) __nv_bfloat16 g_ctxh[M_ * C_],     g_ctxl[M_ * C_];
__device__ __align__(256) __nv_bfloat16 g_hnh [M_ * C_],     g_hnl [M_ * C_];
__device__ __align__(256) __nv_bfloat16 g_ffh [M_ * DFF],    g_ffl [M_ * DFF];
__device__ __align__(256) __nv_bfloat16 g_ah  [ATTNSZ],      g_al  [ATTNSZ];
__device__ __align__(256) __nv_bfloat16 g_wqkvh[3 * C_ * C_], g_wqkvl[3 * C_ * C_];
__device__ __align__(256) __nv_bfloat16 g_wprojh[C_ * C_],    g_wprojl[C_ * C_];
__device__ __align__(256) __nv_bfloat16 g_wfc1h[DFF * C_],    g_wfc1l[DFF * C_];
__device__ __align__(256) __nv_bfloat16 g_wfc2h[C_ * DFF],    g_wfc2l[C_ * DFF];

// ---------------- block reductions ----------------
__device__ __forceinline__ float blockReduceSum(float val, float* shbuf) {
    int lane = threadIdx.x & 31, wid = threadIdx.x >> 5;
#pragma unroll
    for (int o = 16; o > 0; o >>= 1) val += __shfl_xor_sync(0xffffffffu, val, o);
    if (lane == 0) shbuf[wid] = val;
    __syncthreads();
    if (wid == 0) {
        val = (lane < 8) ? shbuf[lane] : 0.0f;
#pragma unroll
        for (int o = 4; o > 0; o >>= 1) val += __shfl_xor_sync(0xffffffffu, val, o);
        if (lane == 0) shbuf[0] = val;
    }
    __syncthreads();
    float r = shbuf[0];
    __syncthreads();
    return r;
}
__device__ __forceinline__ float blockReduceMax(float val, float* shbuf) {
    int lane = threadIdx.x & 31, wid = threadIdx.x >> 5;
#pragma unroll
    for (int o = 16; o > 0; o >>= 1) val = fmaxf(val, __shfl_xor_sync(0xffffffffu, val, o));
    if (lane == 0) shbuf[wid] = val;
    __syncthreads();
    if (wid == 0) {
        val = (lane < 8) ? shbuf[lane] : -INFINITY;
#pragma unroll
        for (int o = 4; o > 0; o >>= 1) val = fmaxf(val, __shfl_xor_sync(0xffffffffu, val, o));
        if (lane == 0) shbuf[0] = val;
    }
    __syncthreads();
    float r = shbuf[0];
    __syncthreads();
    return r;
}

// ---------------- layernorm -> bf16 hi/lo ----------------
__global__ __launch_bounds__(256)
void ln_split_kernel(const float* __restrict__ x, const float* __restrict__ g,
                     const float* __restrict__ b,
                     __nv_bfloat16* __restrict__ hi, __nv_bfloat16* __restrict__ lo) {
    __shared__ float sh[8];
    long long row = blockIdx.x;
    const float* xr = x + row * C_;
    int t = threadIdx.x;
    float v[4];
    float s = 0.0f;
#pragma unroll
    for (int i = 0; i < 4; i++) { v[i] = xr[t + i * 256]; s += v[i]; }
    s = blockReduceSum(s, sh);
    float mu = s * (1.0f / C_);
    float var = 0.0f;
#pragma unroll
    for (int i = 0; i < 4; i++) { float d = v[i] - mu; var += d * d; }
    var = blockReduceSum(var, sh);
    float r = rsqrtf(var * (1.0f / C_) + 1e-5f);
#pragma unroll
    for (int i = 0; i < 4; i++) {
        int c = t + i * 256;
        float o = (v[i] - mu) * r * g[c] + b[c];
        __nv_bfloat16 h = __float2bfloat16(o);
        hi[row * C_ + c] = h;
        lo[row * C_ + c] = __float2bfloat16(o - __bfloat162float(h));
    }
}

// ---------------- softmax + bf16 split (row of 2048) ----------------
__global__ __launch_bounds__(256)
void softmax_split_kernel(float* __restrict__ attn,
                          __nv_bfloat16* __restrict__ hi, __nv_bfloat16* __restrict__ lo) {
    __shared__ float sh[8];
    long long row = blockIdx.x;
    float* p = attn + row * (long long)N_;
    __nv_bfloat16* ph = hi + row * (long long)N_;
    __nv_bfloat16* pl = lo + row * (long long)N_;
    int t = threadIdx.x;
    float v[8];
    float mx = -INFINITY;
#pragma unroll
    for (int i = 0; i < 8; i++) { v[i] = p[t + i * 256]; mx = fmaxf(mx, v[i]); }
    mx = blockReduceMax(mx, sh);
    float s = 0.0f;
#pragma unroll
    for (int i = 0; i < 8; i++) { v[i] = __expf(v[i] - mx); s += v[i]; }
    s = blockReduceSum(s, sh);
    float inv = 1.0f / s;
#pragma unroll
    for (int i = 0; i < 8; i++) {
        int c = t + i * 256;
        float w = v[i] * inv;
        p[c] = w;
        __nv_bfloat16 h = __float2bfloat16(w);
        ph[c] = h;
        pl[c] = __float2bfloat16(w - __bfloat162float(h));
    }
}

// ---------------- fp32 -> bf16 hi/lo split (weights) ----------------
__global__ __launch_bounds__(256)
void split_kernel(const float* __restrict__ src, __nv_bfloat16* __restrict__ hi,
                  __nv_bfloat16* __restrict__ lo, long long n) {
    long long i = ((long long)blockIdx.x * 256 + threadIdx.x) * 4;
    if (i >= n) return;
    float4 v = *(const float4*)(src + i);
    float f[4] = {v.x, v.y, v.z, v.w};
    __nv_bfloat16 h[4], l[4];
#pragma unroll
    for (int j = 0; j < 4; j++) {
        h[j] = __float2bfloat16(f[j]);
        l[j] = __float2bfloat16(f[j] - __bfloat162float(h[j]));
    }
    *(uint2*)(hi + i) = *(uint2*)h;
    *(uint2*)(lo + i) = *(uint2*)l;
}

// ---------------- epilogue ids ----------------
enum { EPI_NONE = 0, EPI_BIAS_GELU = 1, EPI_BIAS_RES = 2, EPI_SCORE = 3 };

// ============================================================================
// WMMA bf16x3 GEMM (ABT): C[M,Nc] = (Ah+Al)[M,K] @ (Bh+Bl)[Nc,K]^T
// 128x128 block, 8 warps (warp tile 32x64), K-chunk 32, double-buffered.
// OSPLIT=1 -> write bf16 hi/lo (Ch,Cl); else fp32 Cf.
// ============================================================================
static constexpr int S1_AH = 0, S1_AL = 5120, S1_BH = 10240, S1_BL = 15360;
static constexpr int S1_STAGE = 20480;                 // elements per stage
static constexpr int S1_SMEM  = 2 * S1_STAGE * 2;      // 81920 bytes

template <int EPI, int OSPLIT>
__global__ __launch_bounds__(256)
void wgemm_abt(const __nv_bfloat16* __restrict__ Ah, const __nv_bfloat16* __restrict__ Al,
               const __nv_bfloat16* __restrict__ Bh, const __nv_bfloat16* __restrict__ Bl,
               float* __restrict__ Cf, __nv_bfloat16* __restrict__ Ch, __nv_bfloat16* __restrict__ Cl,
               int K, int lda, int ldb, int ldc,
               long long aOut, long long aIn, long long bOut, long long bIn,
               long long cOut, long long cIn, int Hdiv,
               const float* __restrict__ bias, const float* __restrict__ resid,
               float scale, const int* __restrict__ mask, int maskld) {
    extern __shared__ char smem_raw[];
    __nv_bfloat16* sm = (__nv_bfloat16*)smem_raw;

    int z = blockIdx.z, zb = z / Hdiv, zh = z % Hdiv;
    Ah += (long long)zb * aOut + (long long)zh * aIn;
    Al += (long long)zb * aOut + (long long)zh * aIn;
    Bh += (long long)zb * bOut + (long long)zh * bIn;
    Bl += (long long)zb * bOut + (long long)zh * bIn;
    long long cz = (long long)zb * cOut + (long long)zh * cIn;
    int m0 = blockIdx.y * 128, n0 = blockIdx.x * 128;

    int t = threadIdx.x, wid = t >> 5;
    int warpM = wid & 3, warpN = wid >> 2;

    int lrow = t >> 1, lcol = (t & 1) * 16;  // global-load mapping (16 bf16 each)
    const __nv_bfloat16* gAh = Ah + (long long)(m0 + lrow) * lda + lcol;
    const __nv_bfloat16* gAl = Al + (long long)(m0 + lrow) * lda + lcol;
    const __nv_bfloat16* gBh = Bh + (long long)(n0 + lrow) * ldb + lcol;
    const __nv_bfloat16* gBl = Bl + (long long)(n0 + lrow) * ldb + lcol;
    int soff = lrow * 40 + lcol;

    wmma::fragment<wmma::accumulator, 16, 16, 16, float> acc[2][4];
#pragma unroll
    for (int i = 0; i < 2; i++)
#pragma unroll
        for (int j = 0; j < 4; j++) wmma::fill_fragment(acc[i][j], 0.0f);

    const int NC = K >> 5;
    // preload chunk 0
    {
        __nv_bfloat16* s = sm;
        *(uint4*)(s + S1_AH + soff)     = *(const uint4*)(gAh);
        *(uint4*)(s + S1_AH + soff + 8) = *(const uint4*)(gAh + 8);
        *(uint4*)(s + S1_AL + soff)     = *(const uint4*)(gAl);
        *(uint4*)(s + S1_AL + soff + 8) = *(const uint4*)(gAl + 8);
        *(uint4*)(s + S1_BH + soff)     = *(const uint4*)(gBh);
        *(uint4*)(s + S1_BH + soff + 8) = *(const uint4*)(gBh + 8);
        *(uint4*)(s + S1_BL + soff)     = *(const uint4*)(gBl);
        *(uint4*)(s + S1_BL + soff + 8) = *(const uint4*)(gBl + 8);
    }
    __syncthreads();

    for (int ch = 0; ch < NC; ch++) {
        uint4 pf[8];
        if (ch + 1 < NC) {
            int kc = (ch + 1) << 5;
            pf[0] = *(const uint4*)(gAh + kc);     pf[1] = *(const uint4*)(gAh + kc + 8);
            pf[2] = *(const uint4*)(gAl + kc);     pf[3] = *(const uint4*)(gAl + kc + 8);
            pf[4] = *(const uint4*)(gBh + kc);     pf[5] = *(const uint4*)(gBh + kc + 8);
            pf[6] = *(const uint4*)(gBl + kc);     pf[7] = *(const uint4*)(gBl + kc + 8);
        }
        const __nv_bfloat16* s = sm + (ch & 1) * S1_STAGE;
#pragma unroll
        for (int ks = 0; ks < 2; ks++) {
#pragma unroll
            for (int mi = 0; mi < 2; mi++) {
                wmma::fragment<wmma::matrix_a, 16, 16, 16, __nv_bfloat16, wmma::row_major> fa_h, fa_l;
                wmma::load_matrix_sync(fa_h, s + S1_AH + (warpM * 32 + mi * 16) * 40 + ks * 16, 40);
                wmma::load_matrix_sync(fa_l, s + S1_AL + (warpM * 32 + mi * 16) * 40 + ks * 16, 40);
#pragma unroll
                for (int ni = 0; ni < 4; ni++) {
                    wmma::fragment<wmma::matrix_b, 16, 16, 16, __nv_bfloat16, wmma::col_major> fb_h, fb_l;
                    wmma::load_matrix_sync(fb_h, s + S1_BH + (warpN * 64 + ni * 16) * 40 + ks * 16, 40);
                    wmma::load_matrix_sync(fb_l, s + S1_BL + (warpN * 64 + ni * 16) * 40 + ks * 16, 40);
                    wmma::mma_sync(acc[mi][ni], fa_h, fb_h, acc[mi][ni]);
                    wmma::mma_sync(acc[mi][ni], fa_h, fb_l, acc[mi][ni]);
                    wmma::mma_sync(acc[mi][ni], fa_l, fb_h, acc[mi][ni]);
                }
            }
        }
        if (ch + 1 < NC) {
            __nv_bfloat16* sn = sm + ((ch + 1) & 1) * S1_STAGE;
            *(uint4*)(sn + S1_AH + soff)     = pf[0]; *(uint4*)(sn + S1_AH + soff + 8) = pf[1];
            *(uint4*)(sn + S1_AL + soff)     = pf[2]; *(uint4*)(sn + S1_AL + soff + 8) = pf[3];
            *(uint4*)(sn + S1_BH + soff)     = pf[4]; *(uint4*)(sn + S1_BH + soff + 8) = pf[5];
            *(uint4*)(sn + S1_BL + soff)     = pf[6]; *(uint4*)(sn + S1_BL + soff + 8) = pf[7];
            __syncthreads();
        }
    }

    // write accumulators through smem (padded ldm=132)
    __syncthreads();
    float* smc = (float*)smem_raw;
#pragma unroll
    for (int mi = 0; mi < 2; mi++)
#pragma unroll
        for (int ni = 0; ni < 4; ni++)
            wmma::store_matrix_sync(&smc[(warpM * 32 + mi * 16) * 132 + warpN * 64 + ni * 16],
                                    acc[mi][ni], 132, wmma::mem_row_major);
    __syncthreads();

    int r  = t >> 1;
    int c0 = (t & 1) * 64;
    int mg = m0 + r;
    long long cbase = cz + (long long)mg * ldc + n0 + c0;
    const int* mrow = (EPI == EPI_SCORE) ? mask + (long long)zb * maskld : nullptr;

#pragma unroll
    for (int j4 = 0; j4 < 64; j4 += 4) {
        float v[4];
#pragma unroll
        for (int q = 0; q < 4; q++) v[q] = smc[r * 132 + c0 + j4 + q];
        if (EPI == EPI_SCORE) {
            int4 mv = *(const int4*)&mrow[n0 + c0 + j4];
            int mm[4] = {mv.x, mv.y, mv.z, mv.w};
#pragma unroll
            for (int q = 0; q < 4; q++) {
                v[q] *= scale;
                if (mm[q] == 0) v[q] = -INFINITY;
            }
        } else if (EPI == EPI_BIAS_GELU) {
            float4 bv = *(const float4*)&bias[n0 + c0 + j4];
            float bb[4] = {bv.x, bv.y, bv.z, bv.w};
#pragma unroll
            for (int q = 0; q < 4; q++) {
                float xv = v[q] + bb[q];
                v[q] = 0.5f * xv * (1.0f + erff(xv * 0.70710678118654752f));
            }
        } else if (EPI == EPI_BIAS_RES) {
            float4 bv = *(const float4*)&bias[n0 + c0 + j4];
            float4 rv = *(const float4*)&resid[cbase + j4];
            v[0] += bv.x + rv.x; v[1] += bv.y + rv.y;
            v[2] += bv.z + rv.z; v[3] += bv.w + rv.w;
        }
        if (OSPLIT) {
            __nv_bfloat16 hv[4], lv[4];
#pragma unroll
            for (int q = 0; q < 4; q++) {
                hv[q] = __float2bfloat16(v[q]);
                lv[q] = __float2bfloat16(v[q] - __bfloat162float(hv[q]));
            }
            *(uint2*)(Ch + cbase + j4) = *(uint2*)hv;
            *(uint2*)(Cl + cbase + j4) = *(uint2*)lv;
        } else {
            *(float4*)&Cf[cbase + j4] = make_float4(v[0], v[1], v[2], v[3]);
        }
    }
}

// ============================================================================
// WMMA bf16x3 GEMM (AB, Nc=64): C[M,64] = (Ah+Al)[M,K] @ (Bh+Bl)[K,64]
// 128x64 block, 8 warps (warp tile 32x32), K-chunk 32, double-buffered.
// Output: bf16 hi/lo split (feeds proj GEMM).
// ============================================================================
static constexpr int S2_AH = 0, S2_AL = 5120, S2_BH = 10240, S2_BL = 12544;
static constexpr int S2_STAGE = 14848;
static constexpr int S2_SMEM  = 2 * S2_STAGE * 2;   // 59392 bytes

__global__ __launch_bounds__(256)
void wgemm_ab64(const __nv_bfloat16* __restrict__ Ah, const __nv_bfloat16* __restrict__ Al,
                const __nv_bfloat16* __restrict__ Bh, const __nv_bfloat16* __restrict__ Bl,
                __nv_bfloat16* __restrict__ Ch, __nv_bfloat16* __restrict__ Cl,
                int K, int lda, int ldb, int ldc,
                long long aOut, long long aIn, long long bOut, long long bIn,
                long long cOut, long long cIn, int Hdiv) {
    extern __shared__ char smem_raw[];
    __nv_bfloat16* sm = (__nv_bfloat16*)smem_raw;

    int z = blockIdx.z, zb = z / Hdiv, zh = z % Hdiv;
    Ah += (long long)zb * aOut + (long long)zh * aIn;
    Al += (long long)zb * aOut + (long long)zh * aIn;
    Bh += (long long)zb * bOut + (long long)zh * bIn;
    Bl += (long long)zb * bOut + (long long)zh * bIn;
    long long cz = (long long)zb * cOut + (long long)zh * cIn;
    int m0 = blockIdx.y * 128;

    int t = threadIdx.x, wid = t >> 5;
    int warpM = wid & 3, warpN = wid >> 2;

    int lrow = t >> 1, lcol = (t & 1) * 16;   // A loads
    const __nv_bfloat16* gAh = Ah + (long long)(m0 + lrow) * lda + lcol;
    const __nv_bfloat16* gAl = Al + (long long)(m0 + lrow) * lda + lcol;
    int aoff = lrow * 40 + lcol;
    int brow = t >> 3, bcol = (t & 7) * 8;    // B loads: 32 x 64
    const __nv_bfloat16* gBh = Bh + (long long)brow * ldb + bcol;
    const __nv_bfloat16* gBl = Bl + (long long)brow * ldb + bcol;
    int boff = brow * 72 + bcol;

    wmma::fragment<wmma::accumulator, 16, 16, 16, float> acc[2][2];
#pragma unroll
    for (int i = 0; i < 2; i++)
#pragma unroll
        for (int j = 0; j < 2; j++) wmma::fill_fragment(acc[i][j], 0.0f);

    const int NC = K >> 5;
    {
        __nv_bfloat16* s = sm;
        *(uint4*)(s + S2_AH + aoff)     = *(const uint4*)(gAh);
        *(uint4*)(s + S2_AH + aoff + 8) = *(const uint4*)(gAh + 8);
        *(uint4*)(s + S2_AL + aoff)     = *(const uint4*)(gAl);
        *(uint4*)(s + S2_AL + aoff + 8) = *(const uint4*)(gAl + 8);
        *(uint4*)(s + S2_BH + boff)     = *(const uint4*)(gBh);
        *(uint4*)(s + S2_BL + boff)     = *(const uint4*)(gBl);
    }
    __syncthreads();

    for (int ch = 0; ch < NC; ch++) {
        uint4 pf[6];
        if (ch + 1 < NC) {
            int kc = (ch + 1) << 5;
            pf[0] = *(const uint4*)(gAh + kc);     pf[1] = *(const uint4*)(gAh + kc + 8);
            pf[2] = *(const uint4*)(gAl + kc);     pf[3] = *(const uint4*)(gAl + kc + 8);
            pf[4] = *(const uint4*)(gBh + (long long)kc * ldb);
            pf[5] = *(const uint4*)(gBl + (long long)kc * ldb);
        }
        const __nv_bfloat16* s = sm + (ch & 1) * S2_STAGE;
#pragma unroll
        for (int ks = 0; ks < 2; ks++) {
#pragma unroll
            for (int mi = 0; mi < 2; mi++) {
                wmma::fragment<wmma::matrix_a, 16, 16, 16, __nv_bfloat16, wmma::row_major> fa_h, fa_l;
                wmma::load_matrix_sync(fa_h, s + S2_AH + (warpM * 32 + mi * 16) * 40 + ks * 16, 40);
                wmma::load_matrix_sync(fa_l, s + S2_AL + (warpM * 32 + mi * 16) * 40 + ks * 16, 40);
#pragma unroll
                for (int ni = 0; ni < 2; ni++) {
                    wmma::fragment<wmma::matrix_b, 16, 16, 16, __nv_bfloat16, wmma::row_major> fb_h, fb_l;
                    wmma::load_matrix_sync(fb_h, s + S2_BH + ks * 16 * 72 + warpN * 32 + ni * 16, 72);
                    wmma::load_matrix_sync(fb_l, s + S2_BL + ks * 16 * 72 + warpN * 32 + ni * 16, 72);
                    wmma::mma_sync(acc[mi][ni], fa_h, fb_h, acc[mi][ni]);
                    wmma::mma_sync(acc[mi][ni], fa_h, fb_l, acc[mi][ni]);
                    wmma::mma_sync(acc[mi][ni], fa_l, fb_h, acc[mi][ni]);
                }
            }
        }
        if (ch + 1 < NC) {
            __nv_bfloat16* sn = sm + ((ch + 1) & 1) * S2_STAGE;
            *(uint4*)(sn + S2_AH + aoff)     = pf[0]; *(uint4*)(sn + S2_AH + aoff + 8) = pf[1];
            *(uint4*)(sn + S2_AL + aoff)     = pf[2]; *(uint4*)(sn + S2_AL + aoff + 8) = pf[3];
            *(uint4*)(sn + S2_BH + boff)     = pf[4];
            *(uint4*)(sn + S2_BL + boff)     = pf[5];
            __syncthreads();
        }
    }

    __syncthreads();
    float* smc = (float*)smem_raw;
#pragma unroll
    for (int mi = 0; mi < 2; mi++)
#pragma unroll
        for (int ni = 0; ni < 2; ni++)
            wmma::store_matrix_sync(&smc[(warpM * 32 + mi * 16) * 68 + warpN * 32 + ni * 16],
                                    acc[mi][ni], 68, wmma::mem_row_major);
    __syncthreads();

    int r  = t >> 1;
    int c0 = (t & 1) * 32;
    long long cbase = cz + (long long)(m0 + r) * ldc + c0;
#pragma unroll
    for (int j4 = 0; j4 < 32; j4 += 4) {
        __nv_bfloat16 hv[4], lv[4];
#pragma unroll
        for (int q = 0; q < 4; q++) {
            float v = smc[r * 68 + c0 + j4 + q];
            hv[q] = __float2bfloat16(v);
            lv[q] = __float2bfloat16(v - __bfloat162float(hv[q]));
        }
        *(uint2*)(Ch + cbase + j4) = *(uint2*)hv;
        *(uint2*)(Cl + cbase + j4) = *(uint2*)lv;
    }
}

// ---------------- launch ----------------
extern "C" void kernel_launch(void* const* d_in, const int* in_sizes, int n_in,
                              void* d_out, int out_size) {
    const float* x      = (const float*)d_in[0];
    const int*   mask   = (const int*)  d_in[1];
    const float* qkv_w  = (const float*)d_in[2];
    const float* proj_w = (const float*)d_in[3];
    const float* proj_b = (const float*)d_in[4];
    const float* ln1_g  = (const float*)d_in[5];
    const float* ln1_b  = (const float*)d_in[6];
    const float* ln2_g  = (const float*)d_in[7];
    const float* ln2_b  = (const float*)d_in[8];
    const float* fc1_w  = (const float*)d_in[9];
    const float* fc1_b  = (const float*)d_in[10];
    const float* fc2_w  = (const float*)d_in[11];
    const float* fc2_b  = (const float*)d_in[12];

    float* out_x = (float*)d_out;

#define GA(sym, var) float* var; cudaGetSymbolAddress((void**)&var, sym)
#define GB(sym, var) __nv_bfloat16* var; cudaGetSymbolAddress((void**)&var, sym)
    GA(g_x1, x1); GA(g_attn_fallback, attn_fb);
    GB(g_xnh, xnh);   GB(g_xnl, xnl);
    GB(g_qkvh, qkvh); GB(g_qkvl, qkvl);
    GB(g_ctxh, ctxh); GB(g_ctxl, ctxl);
    GB(g_hnh, hnh);   GB(g_hnl, hnl);
    GB(g_ffh, ffh);   GB(g_ffl, ffl);
    GB(g_ah, ah);     GB(g_al, al);
    GB(g_wqkvh, wqkvh);   GB(g_wqkvl, wqkvl);
    GB(g_wprojh, wprojh); GB(g_wprojl, wprojl);
    GB(g_wfc1h, wfc1h);   GB(g_wfc1l, wfc1l);
    GB(g_wfc2h, wfc2h);   GB(g_wfc2l, wfc2l);
#undef GA
#undef GB

    float* attn = ((long long)out_size >= XSZ + ATTNSZ) ? (out_x + XSZ) : attn_fb;

    cudaFuncSetAttribute(wgemm_abt<EPI_NONE, 1>,      cudaFuncAttributeMaxDynamicSharedMemorySize, S1_SMEM);
    cudaFuncSetAttribute(wgemm_abt<EPI_SCORE, 0>,     cudaFuncAttributeMaxDynamicSharedMemorySize, S1_SMEM);
    cudaFuncSetAttribute(wgemm_abt<EPI_BIAS_RES, 0>,  cudaFuncAttributeMaxDynamicSharedMemorySize, S1_SMEM);
    cudaFuncSetAttribute(wgemm_abt<EPI_BIAS_GELU, 1>, cudaFuncAttributeMaxDynamicSharedMemorySize, S1_SMEM);
    cudaFuncSetAttribute(wgemm_ab64,                  cudaFuncAttributeMaxDynamicSharedMemorySize, S2_SMEM);

    const float scale = 0.125f;

    auto split = [](const float* s, __nv_bfloat16* h, __nv_bfloat16* l, long long n) {
        split_kernel<<<(unsigned)((n / 4 + 255) / 256), 256>>>(s, h, l, n);
    };

    // weight splits
    split(qkv_w,  wqkvh,  wqkvl,  (long long)3 * C_ * C_);
    split(proj_w, wprojh, wprojl, (long long)C_ * C_);
    split(fc1_w,  wfc1h,  wfc1l,  (long long)DFF * C_);
    split(fc2_w,  wfc2h,  wfc2l,  (long long)C_ * DFF);

    // 1) ln1(x) -> xn hi/lo
    ln_split_kernel<<<M_, 256>>>(x, ln1_g, ln1_b, xnh, xnl);

    // 2) qkv = xn @ qkv_w^T  -> hi/lo split output
    wgemm_abt<EPI_NONE, 1><<<dim3(3 * C_ / 128, M_ / 128, 1), 256, S1_SMEM>>>(
        xnh, xnl, wqkvh, wqkvl, nullptr, qkvh, qkvl, C_, C_, C_, 3 * C_,
        0, 0, 0, 0, 0, 0, 1, nullptr, nullptr, 0.f, nullptr, 0);

    // 3) scores = scale * q @ k^T, masked -> attn fp32
    wgemm_abt<EPI_SCORE, 0><<<dim3(N_ / 128, N_ / 128, B_ * H_), 256, S1_SMEM>>>(
        qkvh, qkvl, qkvh + C_, qkvl + C_, attn, nullptr, nullptr, D_, 3 * C_, 3 * C_, N_,
        (long long)N_ * 3 * C_, D_,
        (long long)N_ * 3 * C_, D_,
        (long long)H_ * N_ * N_, (long long)N_ * N_,
        H_, nullptr, nullptr, scale, mask, N_);

    // 4) softmax + split attn -> (fp32 out, hi/lo for attn@V)
    softmax_split_kernel<<<B_ * H_ * N_, 256>>>(attn, ah, al);

    // 5) ctx = attn @ v -> hi/lo split
    wgemm_ab64<<<dim3(1, N_ / 128, B_ * H_), 256, S2_SMEM>>>(
        ah, al, qkvh + 2 * C_, qkvl + 2 * C_, ctxh, ctxl,
        N_, N_, 3 * C_, C_,
        (long long)H_ * N_ * N_, (long long)N_ * N_,
        (long long)N_ * 3 * C_, D_,
        (long long)N_ * C_, D_,
        H_);

    // 6) x1 = x + ctx @ proj_w^T + proj_b  (fp32)
    wgemm_abt<EPI_BIAS_RES, 0><<<dim3(C_ / 128, M_ / 128, 1), 256, S1_SMEM>>>(
        ctxh, ctxl, wprojh, wprojl, x1, nullptr, nullptr, C_, C_, C_, C_,
        0, 0, 0, 0, 0, 0, 1, proj_b, x, 0.f, nullptr, 0);

    // 7) ln2(x1) -> hn hi/lo
    ln_split_kernel<<<M_, 256>>>(x1, ln2_g, ln2_b, hnh, hnl);

    // 8) ff = gelu(hn @ fc1_w^T + fc1_b) -> hi/lo
    wgemm_abt<EPI_BIAS_GELU, 1><<<dim3(DFF / 128, M_ / 128, 1), 256, S1_SMEM>>>(
        hnh, hnl, wfc1h, wfc1l, nullptr, ffh, ffl, C_, C_, C_, DFF,
        0, 0, 0, 0, 0, 0, 1, fc1_b, nullptr, 0.f, nullptr, 0);

    // 9) out_x = x1 + ff @ fc2_w^T + fc2_b  (fp32)
    wgemm_abt<EPI_BIAS_RES, 0><<<dim3(C_ / 128, M_ / 128, 1), 256, S1_SMEM>>>(
        ffh, ffl, wfc2h, wfc2l, out_x, nullptr, nullptr, DFF, DFF, DFF, C_,
        0, 0, 0, 0, 0, 0, 1, fc2_b, x1, 0.f, nullptr, 0);
}

// round 7
// speedup vs baseline: 1.9207x; 1.1626x over previous
#include <cuda_runtime.h>
#include <cuda_bf16.h>
#include <mma.h>
#include <cstdint>
#include <math.h>

using namespace nvcuda;

// Problem constants
static constexpr int B_  = 2;
static constexpr int N_  = 2048;
static constexpr int C_  = 1024;
static constexpr int H_  = 16;
static constexpr int D_  = 64;
static constexpr int DFF = 4096;
static constexpr int M_  = B_ * N_;
static constexpr long long XSZ   = (long long)B_ * N_ * C_;
static constexpr long long ATTNSZ= (long long)B_ * H_ * N_ * N_;

// ---------------- scratch (device globals) ----------------
__device__ __align__(256) float g_x1 [M_ * C_];
__device__ __align__(256) float g_attn_fallback[ATTNSZ];
__device__ __align__(256) __nv_bfloat16 g_xnh [M_ * C_],     g_xnl [M_ * C_];
__device__ __align__(256) __nv_bfloat16 g_qkvh[M_ * 3 * C_], g_qkvl[M_ * 3 * C_];
__device__ __align__(256) __nv_bfloat16 g_ctxh[M_ * C_],     g_ctxl[M_ * C_];
__device__ __align__(256) __nv_bfloat16 g_hnh [M_ * C_],     g_hnl [M_ * C_];
__device__ __align__(256) __nv_bfloat16 g_ffh [M_ * DFF],    g_ffl [M_ * DFF];
__device__ __align__(256) __nv_bfloat16 g_ah  [ATTNSZ],      g_al  [ATTNSZ];
__device__ __align__(256) __nv_bfloat16 g_wqkvh[3 * C_ * C_], g_wqkvl[3 * C_ * C_];
__device__ __align__(256) __nv_bfloat16 g_wprojh[C_ * C_],    g_wprojl[C_ * C_];
__device__ __align__(256) __nv_bfloat16 g_wfc1h[DFF * C_],    g_wfc1l[DFF * C_];
__device__ __align__(256) __nv_bfloat16 g_wfc2h[C_ * DFF],    g_wfc2l[C_ * DFF];

// ---------------- cp.async helpers ----------------
__device__ __forceinline__ void cp16(void* sdst, const void* gsrc) {
    uint32_t s = (uint32_t)__cvta_generic_to_shared(sdst);
    asm volatile("cp.async.cg.shared.global [%0], [%1], 16;" :: "r"(s), "l"(gsrc));
}
__device__ __forceinline__ void cp_commit() {
    asm volatile("cp.async.commit_group;" ::: "memory");
}
template <int N>
__device__ __forceinline__ void cp_wait() {
    asm volatile("cp.async.wait_group %0;" :: "n"(N) : "memory");
}

// ---------------- block reductions ----------------
__device__ __forceinline__ float blockReduceSum(float val, float* shbuf) {
    int lane = threadIdx.x & 31, wid = threadIdx.x >> 5;
#pragma unroll
    for (int o = 16; o > 0; o >>= 1) val += __shfl_xor_sync(0xffffffffu, val, o);
    if (lane == 0) shbuf[wid] = val;
    __syncthreads();
    if (wid == 0) {
        val = (lane < 8) ? shbuf[lane] : 0.0f;
#pragma unroll
        for (int o = 4; o > 0; o >>= 1) val += __shfl_xor_sync(0xffffffffu, val, o);
        if (lane == 0) shbuf[0] = val;
    }
    __syncthreads();
    float r = shbuf[0];
    __syncthreads();
    return r;
}
__device__ __forceinline__ float blockReduceMax(float val, float* shbuf) {
    int lane = threadIdx.x & 31, wid = threadIdx.x >> 5;
#pragma unroll
    for (int o = 16; o > 0; o >>= 1) val = fmaxf(val, __shfl_xor_sync(0xffffffffu, val, o));
    if (lane == 0) shbuf[wid] = val;
    __syncthreads();
    if (wid == 0) {
        val = (lane < 8) ? shbuf[lane] : -INFINITY;
#pragma unroll
        for (int o = 4; o > 0; o >>= 1) val = fmaxf(val, __shfl_xor_sync(0xffffffffu, val, o));
        if (lane == 0) shbuf[0] = val;
    }
    __syncthreads();
    float r = shbuf[0];
    __syncthreads();
    return r;
}

// ---------------- layernorm -> bf16 hi/lo ----------------
__global__ __launch_bounds__(256)
void ln_split_kernel(const float* __restrict__ x, const float* __restrict__ g,
                     const float* __restrict__ b,
                     __nv_bfloat16* __restrict__ hi, __nv_bfloat16* __restrict__ lo) {
    __shared__ float sh[8];
    long long row = blockIdx.x;
    const float* xr = x + row * C_;
    int t = threadIdx.x;
    float v[4];
    float s = 0.0f;
#pragma unroll
    for (int i = 0; i < 4; i++) { v[i] = xr[t + i * 256]; s += v[i]; }
    s = blockReduceSum(s, sh);
    float mu = s * (1.0f / C_);
    float var = 0.0f;
#pragma unroll
    for (int i = 0; i < 4; i++) { float d = v[i] - mu; var += d * d; }
    var = blockReduceSum(var, sh);
    float r = rsqrtf(var * (1.0f / C_) + 1e-5f);
#pragma unroll
    for (int i = 0; i < 4; i++) {
        int c = t + i * 256;
        float o = (v[i] - mu) * r * g[c] + b[c];
        __nv_bfloat16 h = __float2bfloat16(o);
        hi[row * C_ + c] = h;
        lo[row * C_ + c] = __float2bfloat16(o - __bfloat162float(h));
    }
}

// ---------------- softmax + bf16 split ----------------
__global__ __launch_bounds__(256)
void softmax_split_kernel(float* __restrict__ attn,
                          __nv_bfloat16* __restrict__ hi, __nv_bfloat16* __restrict__ lo) {
    __shared__ float sh[8];
    long long row = blockIdx.x;
    float* p = attn + row * (long long)N_;
    __nv_bfloat16* ph = hi + row * (long long)N_;
    __nv_bfloat16* pl = lo + row * (long long)N_;
    int t = threadIdx.x;
    float v[8];
    float mx = -INFINITY;
#pragma unroll
    for (int i = 0; i < 8; i++) { v[i] = p[t + i * 256]; mx = fmaxf(mx, v[i]); }
    mx = blockReduceMax(mx, sh);
    float s = 0.0f;
#pragma unroll
    for (int i = 0; i < 8; i++) { v[i] = __expf(v[i] - mx); s += v[i]; }
    s = blockReduceSum(s, sh);
    float inv = 1.0f / s;
#pragma unroll
    for (int i = 0; i < 8; i++) {
        int c = t + i * 256;
        float w = v[i] * inv;
        p[c] = w;
        __nv_bfloat16 h = __float2bfloat16(w);
        ph[c] = h;
        pl[c] = __float2bfloat16(w - __bfloat162float(h));
    }
}

// ---------------- fp32 -> bf16 hi/lo split ----------------
__global__ __launch_bounds__(256)
void split_kernel(const float* __restrict__ src, __nv_bfloat16* __restrict__ hi,
                  __nv_bfloat16* __restrict__ lo, long long n) {
    long long i = ((long long)blockIdx.x * 256 + threadIdx.x) * 4;
    if (i >= n) return;
    float4 v = *(const float4*)(src + i);
    float f[4] = {v.x, v.y, v.z, v.w};
    __nv_bfloat16 h[4], l[4];
#pragma unroll
    for (int j = 0; j < 4; j++) {
        h[j] = __float2bfloat16(f[j]);
        l[j] = __float2bfloat16(f[j] - __bfloat162float(h[j]));
    }
    *(uint2*)(hi + i) = *(uint2*)h;
    *(uint2*)(lo + i) = *(uint2*)l;
}

// ---------------- epilogue ids ----------------
enum { EPI_NONE = 0, EPI_BIAS_GELU = 1, EPI_BIAS_RES = 2, EPI_SCORE = 3 };

// ============================================================================
// WMMA bf16x3 GEMM (ABT) with cp.async 2-stage pipeline.
// 128x128 block, 8 warps (32x64 warp tile), K-chunk 32.
// ============================================================================
static constexpr int S1_AH = 0, S1_AL = 5120, S1_BH = 10240, S1_BL = 15360;
static constexpr int S1_STAGE = 20480;
static constexpr int S1_SMEM  = 2 * S1_STAGE * 2;   // 81920 B

template <int EPI, int OSPLIT>
__global__ __launch_bounds__(256, 2)
void wgemm_abt(const __nv_bfloat16* __restrict__ Ah, const __nv_bfloat16* __restrict__ Al,
               const __nv_bfloat16* __restrict__ Bh, const __nv_bfloat16* __restrict__ Bl,
               float* __restrict__ Cf, __nv_bfloat16* __restrict__ Ch, __nv_bfloat16* __restrict__ Cl,
               int K, int lda, int ldb, int ldc,
               long long aOut, long long aIn, long long bOut, long long bIn,
               long long cOut, long long cIn, int Hdiv,
               const float* __restrict__ bias, const float* __restrict__ resid,
               float scale, const int* __restrict__ mask, int maskld) {
    extern __shared__ char smem_raw[];
    __nv_bfloat16* sm = (__nv_bfloat16*)smem_raw;

    int z = blockIdx.z, zb = z / Hdiv, zh = z % Hdiv;
    Ah += (long long)zb * aOut + (long long)zh * aIn;
    Al += (long long)zb * aOut + (long long)zh * aIn;
    Bh += (long long)zb * bOut + (long long)zh * bIn;
    Bl += (long long)zb * bOut + (long long)zh * bIn;
    long long cz = (long long)zb * cOut + (long long)zh * cIn;
    int m0 = blockIdx.y * 128, n0 = blockIdx.x * 128;

    int t = threadIdx.x, wid = t >> 5;
    int warpM = wid & 3, warpN = wid >> 2;

    int lrow = t >> 1, lcol = (t & 1) * 16;
    const __nv_bfloat16* gAh = Ah + (long long)(m0 + lrow) * lda + lcol;
    const __nv_bfloat16* gAl = Al + (long long)(m0 + lrow) * lda + lcol;
    const __nv_bfloat16* gBh = Bh + (long long)(n0 + lrow) * ldb + lcol;
    const __nv_bfloat16* gBl = Bl + (long long)(n0 + lrow) * ldb + lcol;
    int soff = lrow * 40 + lcol;

    wmma::fragment<wmma::accumulator, 16, 16, 16, float> acc[2][4];
#pragma unroll
    for (int i = 0; i < 2; i++)
#pragma unroll
        for (int j = 0; j < 4; j++) wmma::fill_fragment(acc[i][j], 0.0f);

    const int NC = K >> 5;

    auto stage_copy = [&](int ch) {
        __nv_bfloat16* s = sm + (ch & 1) * S1_STAGE;
        int kc = ch << 5;
        cp16(s + S1_AH + soff, gAh + kc); cp16(s + S1_AH + soff + 8, gAh + kc + 8);
        cp16(s + S1_AL + soff, gAl + kc); cp16(s + S1_AL + soff + 8, gAl + kc + 8);
        cp16(s + S1_BH + soff, gBh + kc); cp16(s + S1_BH + soff + 8, gBh + kc + 8);
        cp16(s + S1_BL + soff, gBl + kc); cp16(s + S1_BL + soff + 8, gBl + kc + 8);
    };

    stage_copy(0);
    cp_commit();

    for (int ch = 0; ch < NC; ch++) {
        if (ch + 1 < NC) {
            stage_copy(ch + 1);
            cp_commit();
            cp_wait<1>();
        } else {
            cp_wait<0>();
        }
        __syncthreads();

        const __nv_bfloat16* s = sm + (ch & 1) * S1_STAGE;
#pragma unroll
        for (int ks = 0; ks < 2; ks++) {
            wmma::fragment<wmma::matrix_a, 16, 16, 16, __nv_bfloat16, wmma::row_major> fa_h[2], fa_l[2];
#pragma unroll
            for (int mi = 0; mi < 2; mi++) {
                wmma::load_matrix_sync(fa_h[mi], s + S1_AH + (warpM * 32 + mi * 16) * 40 + ks * 16, 40);
                wmma::load_matrix_sync(fa_l[mi], s + S1_AL + (warpM * 32 + mi * 16) * 40 + ks * 16, 40);
            }
#pragma unroll
            for (int ni = 0; ni < 4; ni++) {
                wmma::fragment<wmma::matrix_b, 16, 16, 16, __nv_bfloat16, wmma::col_major> fb_h, fb_l;
                wmma::load_matrix_sync(fb_h, s + S1_BH + (warpN * 64 + ni * 16) * 40 + ks * 16, 40);
                wmma::load_matrix_sync(fb_l, s + S1_BL + (warpN * 64 + ni * 16) * 40 + ks * 16, 40);
#pragma unroll
                for (int mi = 0; mi < 2; mi++) {
                    wmma::mma_sync(acc[mi][ni], fa_h[mi], fb_h, acc[mi][ni]);
                    wmma::mma_sync(acc[mi][ni], fa_h[mi], fb_l, acc[mi][ni]);
                    wmma::mma_sync(acc[mi][ni], fa_l[mi], fb_h, acc[mi][ni]);
                }
            }
        }
        __syncthreads();
    }

    // epilogue via smem (ldm=132)
    float* smc = (float*)smem_raw;
#pragma unroll
    for (int mi = 0; mi < 2; mi++)
#pragma unroll
        for (int ni = 0; ni < 4; ni++)
            wmma::store_matrix_sync(&smc[(warpM * 32 + mi * 16) * 132 + warpN * 64 + ni * 16],
                                    acc[mi][ni], 132, wmma::mem_row_major);
    __syncthreads();

    int r  = t >> 1;
    int c0 = (t & 1) * 64;
    int mg = m0 + r;
    long long cbase = cz + (long long)mg * ldc + n0 + c0;
    const int* mrow = (EPI == EPI_SCORE) ? mask + (long long)zb * maskld : nullptr;

#pragma unroll
    for (int j4 = 0; j4 < 64; j4 += 4) {
        float v[4];
#pragma unroll
        for (int q = 0; q < 4; q++) v[q] = smc[r * 132 + c0 + j4 + q];
        if (EPI == EPI_SCORE) {
            int4 mv = *(const int4*)&mrow[n0 + c0 + j4];
            int mm[4] = {mv.x, mv.y, mv.z, mv.w};
#pragma unroll
            for (int q = 0; q < 4; q++) {
                v[q] *= scale;
                if (mm[q] == 0) v[q] = -INFINITY;
            }
        } else if (EPI == EPI_BIAS_GELU) {
            float4 bv = *(const float4*)&bias[n0 + c0 + j4];
            float bb[4] = {bv.x, bv.y, bv.z, bv.w};
#pragma unroll
            for (int q = 0; q < 4; q++) {
                float xv = v[q] + bb[q];
                v[q] = 0.5f * xv * (1.0f + erff(xv * 0.70710678118654752f));
            }
        } else if (EPI == EPI_BIAS_RES) {
            float4 bv = *(const float4*)&bias[n0 + c0 + j4];
            float4 rv = *(const float4*)&resid[cbase + j4];
            v[0] += bv.x + rv.x; v[1] += bv.y + rv.y;
            v[2] += bv.z + rv.z; v[3] += bv.w + rv.w;
        }
        if (OSPLIT) {
            __nv_bfloat16 hv[4], lv[4];
#pragma unroll
            for (int q = 0; q < 4; q++) {
                hv[q] = __float2bfloat16(v[q]);
                lv[q] = __float2bfloat16(v[q] - __bfloat162float(hv[q]));
            }
            *(uint2*)(Ch + cbase + j4) = *(uint2*)hv;
            *(uint2*)(Cl + cbase + j4) = *(uint2*)lv;
        } else {
            *(float4*)&Cf[cbase + j4] = make_float4(v[0], v[1], v[2], v[3]);
        }
    }
}

// ============================================================================
// WMMA bf16x3 GEMM (AB, Nc=64) with cp.async 2-stage pipeline.
// ============================================================================
static constexpr int S2_AH = 0, S2_AL = 5120, S2_BH = 10240, S2_BL = 12544;
static constexpr int S2_STAGE = 14848;
static constexpr int S2_SMEM  = 2 * S2_STAGE * 2;   // 59392 B

__global__ __launch_bounds__(256, 2)
void wgemm_ab64(const __nv_bfloat16* __restrict__ Ah, const __nv_bfloat16* __restrict__ Al,
                const __nv_bfloat16* __restrict__ Bh, const __nv_bfloat16* __restrict__ Bl,
                __nv_bfloat16* __restrict__ Ch, __nv_bfloat16* __restrict__ Cl,
                int K, int lda, int ldb, int ldc,
                long long aOut, long long aIn, long long bOut, long long bIn,
                long long cOut, long long cIn, int Hdiv) {
    extern __shared__ char smem_raw[];
    __nv_bfloat16* sm = (__nv_bfloat16*)smem_raw;

    int z = blockIdx.z, zb = z / Hdiv, zh = z % Hdiv;
    Ah += (long long)zb * aOut + (long long)zh * aIn;
    Al += (long long)zb * aOut + (long long)zh * aIn;
    Bh += (long long)zb * bOut + (long long)zh * bIn;
    Bl += (long long)zb * bOut + (long long)zh * bIn;
    long long cz = (long long)zb * cOut + (long long)zh * cIn;
    int m0 = blockIdx.y * 128;

    int t = threadIdx.x, wid = t >> 5;
    int warpM = wid & 3, warpN = wid >> 2;

    int lrow = t >> 1, lcol = (t & 1) * 16;
    const __nv_bfloat16* gAh = Ah + (long long)(m0 + lrow) * lda + lcol;
    const __nv_bfloat16* gAl = Al + (long long)(m0 + lrow) * lda + lcol;
    int aoff = lrow * 40 + lcol;
    int brow = t >> 3, bcol = (t & 7) * 8;
    const __nv_bfloat16* gBh = Bh + (long long)brow * ldb + bcol;
    const __nv_bfloat16* gBl = Bl + (long long)brow * ldb + bcol;
    int boff = brow * 72 + bcol;

    wmma::fragment<wmma::accumulator, 16, 16, 16, float> acc[2][2];
#pragma unroll
    for (int i = 0; i < 2; i++)
#pragma unroll
        for (int j = 0; j < 2; j++) wmma::fill_fragment(acc[i][j], 0.0f);

    const int NC = K >> 5;

    auto stage_copy = [&](int ch) {
        __nv_bfloat16* s = sm + (ch & 1) * S2_STAGE;
        int kc = ch << 5;
        cp16(s + S2_AH + aoff, gAh + kc); cp16(s + S2_AH + aoff + 8, gAh + kc + 8);
        cp16(s + S2_AL + aoff, gAl + kc); cp16(s + S2_AL + aoff + 8, gAl + kc + 8);
        cp16(s + S2_BH + boff, gBh + (long long)kc * ldb);
        cp16(s + S2_BL + boff, gBl + (long long)kc * ldb);
    };

    stage_copy(0);
    cp_commit();

    for (int ch = 0; ch < NC; ch++) {
        if (ch + 1 < NC) {
            stage_copy(ch + 1);
            cp_commit();
            cp_wait<1>();
        } else {
            cp_wait<0>();
        }
        __syncthreads();

        const __nv_bfloat16* s = sm + (ch & 1) * S2_STAGE;
#pragma unroll
        for (int ks = 0; ks < 2; ks++) {
            wmma::fragment<wmma::matrix_a, 16, 16, 16, __nv_bfloat16, wmma::row_major> fa_h[2], fa_l[2];
#pragma unroll
            for (int mi = 0; mi < 2; mi++) {
                wmma::load_matrix_sync(fa_h[mi], s + S2_AH + (warpM * 32 + mi * 16) * 40 + ks * 16, 40);
                wmma::load_matrix_sync(fa_l[mi], s + S2_AL + (warpM * 32 + mi * 16) * 40 + ks * 16, 40);
            }
#pragma unroll
            for (int ni = 0; ni < 2; ni++) {
                wmma::fragment<wmma::matrix_b, 16, 16, 16, __nv_bfloat16, wmma::row_major> fb_h, fb_l;
                wmma::load_matrix_sync(fb_h, s + S2_BH + ks * 16 * 72 + warpN * 32 + ni * 16, 72);
                wmma::load_matrix_sync(fb_l, s + S2_BL + ks * 16 * 72 + warpN * 32 + ni * 16, 72);
#pragma unroll
                for (int mi = 0; mi < 2; mi++) {
                    wmma::mma_sync(acc[mi][ni], fa_h[mi], fb_h, acc[mi][ni]);
                    wmma::mma_sync(acc[mi][ni], fa_h[mi], fb_l, acc[mi][ni]);
                    wmma::mma_sync(acc[mi][ni], fa_l[mi], fb_h, acc[mi][ni]);
                }
            }
        }
        __syncthreads();
    }

    float* smc = (float*)smem_raw;
#pragma unroll
    for (int mi = 0; mi < 2; mi++)
#pragma unroll
        for (int ni = 0; ni < 2; ni++)
            wmma::store_matrix_sync(&smc[(warpM * 32 + mi * 16) * 68 + warpN * 32 + ni * 16],
                                    acc[mi][ni], 68, wmma::mem_row_major);
    __syncthreads();

    int r  = t >> 1;
    int c0 = (t & 1) * 32;
    long long cbase = cz + (long long)(m0 + r) * ldc + c0;
#pragma unroll
    for (int j4 = 0; j4 < 32; j4 += 4) {
        __nv_bfloat16 hv[4], lv[4];
#pragma unroll
        for (int q = 0; q < 4; q++) {
            float v = smc[r * 68 + c0 + j4 + q];
            hv[q] = __float2bfloat16(v);
            lv[q] = __float2bfloat16(v - __bfloat162float(hv[q]));
        }
        *(uint2*)(Ch + cbase + j4) = *(uint2*)hv;
        *(uint2*)(Cl + cbase + j4) = *(uint2*)lv;
    }
}

// ---------------- launch ----------------
extern "C" void kernel_launch(void* const* d_in, const int* in_sizes, int n_in,
                              void* d_out, int out_size) {
    const float* x      = (const float*)d_in[0];
    const int*   mask   = (const int*)  d_in[1];
    const float* qkv_w  = (const float*)d_in[2];
    const float* proj_w = (const float*)d_in[3];
    const float* proj_b = (const float*)d_in[4];
    const float* ln1_g  = (const float*)d_in[5];
    const float* ln1_b  = (const float*)d_in[6];
    const float* ln2_g  = (const float*)d_in[7];
    const float* ln2_b  = (const float*)d_in[8];
    const float* fc1_w  = (const float*)d_in[9];
    const float* fc1_b  = (const float*)d_in[10];
    const float* fc2_w  = (const float*)d_in[11];
    const float* fc2_b  = (const float*)d_in[12];

    float* out_x = (float*)d_out;

#define GA(sym, var) float* var; cudaGetSymbolAddress((void**)&var, sym)
#define GB(sym, var) __nv_bfloat16* var; cudaGetSymbolAddress((void**)&var, sym)
    GA(g_x1, x1); GA(g_attn_fallback, attn_fb);
    GB(g_xnh, xnh);   GB(g_xnl, xnl);
    GB(g_qkvh, qkvh); GB(g_qkvl, qkvl);
    GB(g_ctxh, ctxh); GB(g_ctxl, ctxl);
    GB(g_hnh, hnh);   GB(g_hnl, hnl);
    GB(g_ffh, ffh);   GB(g_ffl, ffl);
    GB(g_ah, ah);     GB(g_al, al);
    GB(g_wqkvh, wqkvh);   GB(g_wqkvl, wqkvl);
    GB(g_wprojh, wprojh); GB(g_wprojl, wprojl);
    GB(g_wfc1h, wfc1h);   GB(g_wfc1l, wfc1l);
    GB(g_wfc2h, wfc2h);   GB(g_wfc2l, wfc2l);
#undef GA
#undef GB

    float* attn = ((long long)out_size >= XSZ + ATTNSZ) ? (out_x + XSZ) : attn_fb;

    cudaFuncSetAttribute(wgemm_abt<EPI_NONE, 1>,      cudaFuncAttributeMaxDynamicSharedMemorySize, S1_SMEM);
    cudaFuncSetAttribute(wgemm_abt<EPI_SCORE, 0>,     cudaFuncAttributeMaxDynamicSharedMemorySize, S1_SMEM);
    cudaFuncSetAttribute(wgemm_abt<EPI_BIAS_RES, 0>,  cudaFuncAttributeMaxDynamicSharedMemorySize, S1_SMEM);
    cudaFuncSetAttribute(wgemm_abt<EPI_BIAS_GELU, 1>, cudaFuncAttributeMaxDynamicSharedMemorySize, S1_SMEM);
    cudaFuncSetAttribute(wgemm_ab64,                  cudaFuncAttributeMaxDynamicSharedMemorySize, S2_SMEM);

    const float scale = 0.125f;

    auto split = [](const float* s, __nv_bfloat16* h, __nv_bfloat16* l, long long n) {
        split_kernel<<<(unsigned)((n / 4 + 255) / 256), 256>>>(s, h, l, n);
    };

    split(qkv_w,  wqkvh,  wqkvl,  (long long)3 * C_ * C_);
    split(proj_w, wprojh, wprojl, (long long)C_ * C_);
    split(fc1_w,  wfc1h,  wfc1l,  (long long)DFF * C_);
    split(fc2_w,  wfc2h,  wfc2l,  (long long)C_ * DFF);

    // 1) ln1
    ln_split_kernel<<<M_, 256>>>(x, ln1_g, ln1_b, xnh, xnl);

    // 2) qkv
    wgemm_abt<EPI_NONE, 1><<<dim3(3 * C_ / 128, M_ / 128, 1), 256, S1_SMEM>>>(
        xnh, xnl, wqkvh, wqkvl, nullptr, qkvh, qkvl, C_, C_, C_, 3 * C_,
        0, 0, 0, 0, 0, 0, 1, nullptr, nullptr, 0.f, nullptr, 0);

    // 3) scores
    wgemm_abt<EPI_SCORE, 0><<<dim3(N_ / 128, N_ / 128, B_ * H_), 256, S1_SMEM>>>(
        qkvh, qkvl, qkvh + C_, qkvl + C_, attn, nullptr, nullptr, D_, 3 * C_, 3 * C_, N_,
        (long long)N_ * 3 * C_, D_,
        (long long)N_ * 3 * C_, D_,
        (long long)H_ * N_ * N_, (long long)N_ * N_,
        H_, nullptr, nullptr, scale, mask, N_);

    // 4) softmax + split
    softmax_split_kernel<<<B_ * H_ * N_, 256>>>(attn, ah, al);

    // 5) ctx = attn @ v
    wgemm_ab64<<<dim3(1, N_ / 128, B_ * H_), 256, S2_SMEM>>>(
        ah, al, qkvh + 2 * C_, qkvl + 2 * C_, ctxh, ctxl,
        N_, N_, 3 * C_, C_,
        (long long)H_ * N_ * N_, (long long)N_ * N_,
        (long long)N_ * 3 * C_, D_,
        (long long)N_ * C_, D_,
        H_);

    // 6) x1 = x + ctx @ proj_w^T + proj_b
    wgemm_abt<EPI_BIAS_RES, 0><<<dim3(C_ / 128, M_ / 128, 1), 256, S1_SMEM>>>(
        ctxh, ctxl, wprojh, wprojl, x1, nullptr, nullptr, C_, C_, C_, C_,
        0, 0, 0, 0, 0, 0, 1, proj_b, x, 0.f, nullptr, 0);

    // 7) ln2
    ln_split_kernel<<<M_, 256>>>(x1, ln2_g, ln2_b, hnh, hnl);

    // 8) fc1 + gelu
    wgemm_abt<EPI_BIAS_GELU, 1><<<dim3(DFF / 128, M_ / 128, 1), 256, S1_SMEM>>>(
        hnh, hnl, wfc1h, wfc1l, nullptr, ffh, ffl, C_, C_, C_, DFF,
        0, 0, 0, 0, 0, 0, 1, fc1_b, nullptr, 0.f, nullptr, 0);

    // 9) fc2 + residual
    wgemm_abt<EPI_BIAS_RES, 0><<<dim3(C_ / 128, M_ / 128, 1), 256, S1_SMEM>>>(
        ffh, ffl, wfc2h, wfc2l, out_x, nullptr, nullptr, DFF, DFF, DFF, C_,
        0, 0, 0, 0, 0, 0, 1, fc2_b, x1, 0.f, nullptr, 0);
}